// round 11
// baseline (speedup 1.0000x reference)
#include <cuda_runtime.h>
#include <math.h>

#define NN 512
#define D 32
#define TI 16
#define TJ 8
#define TE 128

typedef unsigned long long u64;

// packed f32x2 helpers (sm_103a; PTX ISA f32x2 ops)
#define FMA2ACC(acc, a, b) \
    asm("fma.rn.f32x2 %0, %1, %2, %0;" : "+l"(acc) : "l"(a), "l"(b))
#define PACK2(d, lo, hi) \
    asm("mov.b64 %0, {%1, %2};" : "=l"(d) : "f"(lo), "f"(hi))
#define UNPACK2(lo, hi, s) \
    asm("mov.b64 {%0, %1}, %2;" : "=f"(lo), "=f"(hi) : "l"(s))

// scratch (no allocation allowed)
__device__ float g_h[2][NN * D];
__device__ float g_Ai[NN * 64];
__device__ float g_Bj[NN * 64];
__device__ float g_ms[NN * D];
// pre-transposed edge-MLP weights (built once per graph replay in step0)
__device__ float g_W2t[64 * 68];   // W2t[k][o], padded stride 68
__device__ float g_W3t[64 * 36];   // W3t[k][c], padded stride 36
__device__ float g_wj[64];         // W1[:,64] gathered

// ---- Step-0: closed-form pre-factor (h0 = 0) + one-time weight transpose --
//   Ai[n][k] = b[n]*wbi[k];  Bj[n][k] = b[n]*wbj[k] + b1[k]
// Also zeroes g_h[0]/g_ms and stages W2t/W3t/wj so edge CTAs copy linearly.
__global__ void step0_kernel(const float* __restrict__ b,
                             const float* __restrict__ W1,
                             const float* __restrict__ b1,
                             const float* __restrict__ W2,
                             const float* __restrict__ W3) {
    int idx = blockIdx.x * 256 + threadIdx.x;   // 0 .. 32767
    int n = idx >> 6, k = idx & 63;
    float bn = b[n];
    g_Ai[n * 64 + k] = bn * W1[k * 67 + 65];
    g_Bj[n * 64 + k] = bn * W1[k * 67 + 66] + b1[k];
    if (idx < NN * 32) { g_ms[idx] = 0.f; g_h[0][idx] = 0.f; }
    if (idx < 64 * 64) {                       // W2[o][k] -> W2t[k][o]
        int o = idx >> 6, kk = idx & 63;
        g_W2t[kk * 68 + o] = W2[idx];
    }
    if (idx < 32 * 64) {                       // W3[c][k] -> W3t[k][c]
        int c = idx >> 6, kk = idx & 63;
        g_W3t[kk * 36 + c] = W3[idx];
    }
    if (idx < 64) g_wj[idx] = W1[idx * 67 + 64];
}

// ---- Edge MLP as staged smem GEMM, 512 threads/CTA ------------------------
// Tile = 16 i x 8 j = 128 edges; 2 i-tiles per CTA, Ai/J register-prefetched.
// Phase A: m1 to smem. Phase B: m2 = relu(m1@W2^T+b2), 4e x 4o register tiles
// (f32x2 k-pair packed), float4 stores. Phase C: msg = relu(m2@W3^T+b3),
// 16 warps x 2c, warp-local i-reduction, atomics to g_ms.
#define SM_M1   0        // [128][64]
#define SM_M2T  8192     // [64][132]
#define SM_W2T  16640    // [64][68]   W2t[k][o]
#define SM_W3T  20992    // [64][36]   W3t[k][c]
#define SM_AIS  23296    // [16][64]
#define SM_BJS  24320    // [8][64]
#define SM_JS   24832    // [128]
#define SM_WJS  24960    // [64]
#define SM_B2S  25024    // [64]
#define SM_B3S  25088    // [32]
#define SM_FLOATS 25120
#define SM_BYTES (SM_FLOATS * 4)

__global__ __launch_bounds__(512, 1)
void edge_kernel(const float* __restrict__ J,
                 const float* __restrict__ b2, const float* __restrict__ b3) {
    extern __shared__ float sm[];
    int t = threadIdx.x;
    int j0 = blockIdx.x * TJ;

    // --- prefetch tile 0's Ai (2 floats/thread) + J (1 float, t<128) -------
    int i0_0 = blockIdx.y * (2 * TI);
    float pfA0 = g_Ai[i0_0 * 64 + t];          // idx t       (0..511)
    float pfA1 = g_Ai[i0_0 * 64 + 512 + t];    // idx 512+t
    float pfJ = 0.f;
    if (t < TE) pfJ = J[(i0_0 + (t >> 3)) * NN + j0 + (t & 7)];

    // weights pre-transposed in global: linear copy, coalesced + conflict-free
    for (int idx = t; idx < 64 * 68; idx += 512) sm[SM_W2T + idx] = g_W2t[idx];
    for (int idx = t; idx < 64 * 36; idx += 512) sm[SM_W3T + idx] = g_W3t[idx];
    if (t < 64) { sm[SM_WJS + t] = g_wj[t]; sm[SM_B2S + t] = b2[t]; }
    if (t < 32) sm[SM_B3S + t] = b3[t];
    for (int idx = t; idx < TJ * 64; idx += 512)
        sm[SM_BJS + idx] = g_Bj[j0 * 64 + idx];

    for (int ii = 0; ii < 2; ii++) {
        __syncthreads();   // orders fills; protects AIS/JS/M1/M2T across iters
        // store prefetched tile data to smem
        sm[SM_AIS + t]       = pfA0;
        sm[SM_AIS + 512 + t] = pfA1;
        if (t < TE) sm[SM_JS + t] = pfJ;
        // prefetch NEXT tile (consumed ~6k cycles later; latency fully hidden)
        if (ii == 0) {
            int i0n = i0_0 + TI;
            pfA0 = g_Ai[i0n * 64 + t];
            pfA1 = g_Ai[i0n * 64 + 512 + t];
            if (t < TE) pfJ = J[(i0n + (t >> 3)) * NN + j0 + (t & 7)];
        }
        __syncthreads();

        // Phase A: m1[e][k] = relu(Ai + Bj + J*wJ);  e = i*8 + j
        for (int idx = t; idx < TE * 64; idx += 512) {
            int e = idx >> 6, k = idx & 63;
            float v = sm[SM_AIS + (e >> 3) * 64 + k] + sm[SM_BJS + (e & 7) * 64 + k]
                    + sm[SM_JS + e] * sm[SM_WJS + k];
            sm[SM_M1 + idx] = fmaxf(v, 0.f);
        }
        __syncthreads();

        // Phase B: m2t[o][e] = relu(m1 @ W2^T + b2); 4e x 4o per thread
        {
            int og = t & 15, eg = t >> 4;      // og 0..15, eg 0..31
            u64 acc[4][4];
#pragma unroll
            for (int ee = 0; ee < 4; ee++)
#pragma unroll
                for (int oo = 0; oo < 4; oo++) acc[ee][oo] = 0ull;

#pragma unroll 4
            for (int kq = 0; kq < 16; kq++) {
                int k0 = kq * 4;
                ulonglong2 m1v[4];
#pragma unroll
                for (int ee = 0; ee < 4; ee++)
                    m1v[ee] = *(const ulonglong2*)&sm[SM_M1 + (eg * 4 + ee) * 64 + k0];
                float4 wr0 = *(const float4*)&sm[SM_W2T + (k0 + 0) * 68 + og * 4];
                float4 wr1 = *(const float4*)&sm[SM_W2T + (k0 + 1) * 68 + og * 4];
                float4 wr2 = *(const float4*)&sm[SM_W2T + (k0 + 2) * 68 + og * 4];
                float4 wr3 = *(const float4*)&sm[SM_W2T + (k0 + 3) * 68 + og * 4];
                u64 wpA[4], wpB[4];
                PACK2(wpA[0], wr0.x, wr1.x); PACK2(wpA[1], wr0.y, wr1.y);
                PACK2(wpA[2], wr0.z, wr1.z); PACK2(wpA[3], wr0.w, wr1.w);
                PACK2(wpB[0], wr2.x, wr3.x); PACK2(wpB[1], wr2.y, wr3.y);
                PACK2(wpB[2], wr2.z, wr3.z); PACK2(wpB[3], wr2.w, wr3.w);
#pragma unroll
                for (int ee = 0; ee < 4; ee++) {
#pragma unroll
                    for (int oo = 0; oo < 4; oo++) {
                        FMA2ACC(acc[ee][oo], wpA[oo], m1v[ee].x);
                        FMA2ACC(acc[ee][oo], wpB[oo], m1v[ee].y);
                    }
                }
            }
            // float4 store per o: e-values eg*4..eg*4+3 contiguous in M2T rows
#pragma unroll
            for (int oo = 0; oo < 4; oo++) {
                int o = og * 4 + oo;
                float bb = sm[SM_B2S + o];
                float4 f;
                float lo, hi;
                UNPACK2(lo, hi, acc[0][oo]); f.x = fmaxf(lo + hi + bb, 0.f);
                UNPACK2(lo, hi, acc[1][oo]); f.y = fmaxf(lo + hi + bb, 0.f);
                UNPACK2(lo, hi, acc[2][oo]); f.z = fmaxf(lo + hi + bb, 0.f);
                UNPACK2(lo, hi, acc[3][oo]); f.w = fmaxf(lo + hi + bb, 0.f);
                *(float4*)&sm[SM_M2T + o * 132 + eg * 4] = f;
            }
        }
        __syncthreads();

        // Phase C: msg = relu(m2 @ W3^T + b3); 16 warps x 2c; reduce over i
        {
            int w = t >> 5, l = t & 31;   // warp w -> c = 2w,2w+1; lane l -> e = 4l..4l+3
            u64 accp[2][2];
            accp[0][0] = accp[0][1] = accp[1][0] = accp[1][1] = 0ull;

#pragma unroll 4
            for (int k = 0; k < 64; k++) {
                ulonglong2 m2v = *(const ulonglong2*)&sm[SM_M2T + k * 132 + l * 4];
                float2 w3v = *(const float2*)&sm[SM_W3T + k * 36 + w * 2];
                u64 wb0, wb1;
                PACK2(wb0, w3v.x, w3v.x); PACK2(wb1, w3v.y, w3v.y);
                FMA2ACC(accp[0][0], wb0, m2v.x); FMA2ACC(accp[0][1], wb0, m2v.y);
                FMA2ACC(accp[1][0], wb1, m2v.x); FMA2ACC(accp[1][1], wb1, m2v.y);
            }
            float v[2][4];
#pragma unroll
            for (int cc = 0; cc < 2; cc++) {
                float bb = sm[SM_B3S + w * 2 + cc];
                float lo, hi;
                UNPACK2(lo, hi, accp[cc][0]);
                v[cc][0] = fmaxf(lo + bb, 0.f); v[cc][1] = fmaxf(hi + bb, 0.f);
                UNPACK2(lo, hi, accp[cc][1]);
                v[cc][2] = fmaxf(lo + bb, 0.f); v[cc][3] = fmaxf(hi + bb, 0.f);
            }
            // lane l: i = l>>1 (bits 1..4), j = 4*(l&1)+q. Reduce over i.
#pragma unroll
            for (int cc = 0; cc < 2; cc++)
#pragma unroll
                for (int q = 0; q < 4; q++) {
                    float x = v[cc][q];
                    x += __shfl_xor_sync(0xffffffffu, x, 2);
                    x += __shfl_xor_sync(0xffffffffu, x, 4);
                    x += __shfl_xor_sync(0xffffffffu, x, 8);
                    x += __shfl_xor_sync(0xffffffffu, x, 16);
                    v[cc][q] = x;
                }
            if (l < 2) {
#pragma unroll
                for (int cc = 0; cc < 2; cc++)
#pragma unroll
                    for (int q = 0; q < 4; q++)
                        atomicAdd(&g_ms[(j0 + l * 4 + q) * 32 + w * 2 + cc], v[cc][q]);
            }
        }
    }
}

// ---- Fused GRU + next-step pre-factor: WARP-PER-NODE, 64 CTAs -------------
#define GN_WIHT 0                    // [64][97]  Wih^T
#define GN_WHHT 6208                 // [32][97]  Whh^T
#define GN_W1T  9312                 // [64][65]  W1^T (cols 0..63)
#define GN_B1   13472
#define GN_WBI  13536
#define GN_WBJ  13600
#define GN_BIH  13664
#define GN_BHH  13760
#define GN_HB   13856                // 8*32
#define GN_MSB  14112                // 8*32
#define GN_HNB  14368                // 8*32
#define GN_FLOATS 14624
#define GN_BYTES (GN_FLOATS * 4)

__global__ __launch_bounds__(256, 1)
void gru_node_kernel(const float* __restrict__ Wih, const float* __restrict__ Whh,
                     const float* __restrict__ bih, const float* __restrict__ bhh,
                     const float* __restrict__ b,   const float* __restrict__ W1,
                     const float* __restrict__ b1,  int cur) {
    extern __shared__ float sm[];
    int t = threadIdx.x;
    for (int idx = t; idx < 96 * 64; idx += 256) {
        int q = idx >> 6, d = idx & 63;
        sm[GN_WIHT + d * 97 + q] = Wih[idx];
    }
    for (int idx = t; idx < 96 * 32; idx += 256) {
        int q = idx >> 5, d = idx & 31;
        sm[GN_WHHT + d * 97 + q] = Whh[idx];
    }
    for (int idx = t; idx < 64 * 64; idx += 256) {
        int k = idx >> 6, d = idx & 63;
        sm[GN_W1T + d * 65 + k] = W1[k * 67 + d];
    }
    if (t < 64) {
        sm[GN_B1 + t]  = b1[t];
        sm[GN_WBI + t] = W1[t * 67 + 65];
        sm[GN_WBJ + t] = W1[t * 67 + 66];
    }
    if (t < 96) { sm[GN_BIH + t] = bih[t]; sm[GN_BHH + t] = bhh[t]; }

    int w = t >> 5, l = t & 31;
    int n = blockIdx.x * 8 + w;
    int nxt = cur ^ 1;
    float hl  = g_h[cur][n * 32 + l];
    float msl = g_ms[n * 32 + l];
    sm[GN_HB  + w * 32 + l] = hl;
    sm[GN_MSB + w * 32 + l] = msl;
    __syncthreads();

    float gir = sm[GN_BIH + l], giz = sm[GN_BIH + 32 + l], gin = sm[GN_BIH + 64 + l];
    float ghr = sm[GN_BHH + l], ghz = sm[GN_BHH + 32 + l], ghn = sm[GN_BHH + 64 + l];
    const float* hb = &sm[GN_HB  + w * 32];
    const float* mb = &sm[GN_MSB + w * 32];
#pragma unroll 8
    for (int d = 0; d < 32; d++) {
        float hd = hb[d], md = mb[d];
        const float* c1 = &sm[GN_WIHT + d * 97];
        const float* c2 = &sm[GN_WIHT + (32 + d) * 97];
        gir = fmaf(c1[l],      hd, gir); gir = fmaf(c2[l],      md, gir);
        giz = fmaf(c1[32 + l], hd, giz); giz = fmaf(c2[32 + l], md, giz);
        gin = fmaf(c1[64 + l], hd, gin); gin = fmaf(c2[64 + l], md, gin);
        const float* c3 = &sm[GN_WHHT + d * 97];
        ghr = fmaf(c3[l],      hd, ghr);
        ghz = fmaf(c3[32 + l], hd, ghz);
        ghn = fmaf(c3[64 + l], hd, ghn);
    }
    float r  = 1.f / (1.f + expf(-(gir + ghr)));
    float z  = 1.f / (1.f + expf(-(giz + ghz)));
    float ng = tanhf(gin + r * ghn);
    float hn = (1.f - z) * ng + z * hl;
    g_h[nxt][n * 32 + l] = hn;
    sm[GN_HNB + w * 32 + l] = hn;
    g_ms[n * 32 + l] = 0.f;
    __syncwarp();

    float bn = b[n];
    const float* hnb = &sm[GN_HNB + w * 32];
#pragma unroll
    for (int kk = 0; kk < 2; kk++) {
        int k = l + kk * 32;
        float a = bn * sm[GN_WBI + k];
        float c = bn * sm[GN_WBJ + k] + sm[GN_B1 + k];
#pragma unroll 8
        for (int d = 0; d < 32; d++) {
            float hd = hnb[d];
            a = fmaf(sm[GN_W1T + d * 65 + k],        hd, a);
            c = fmaf(sm[GN_W1T + (32 + d) * 65 + k], hd, c);
        }
        g_Ai[n * 64 + k] = a;
        g_Bj[n * 64 + k] = c;
    }
}

// ---- Readout MLP + sigmoid: WARP-PER-NODE, 64 CTAs ------------------------
__global__ __launch_bounds__(256)
void readout_kernel(const float* __restrict__ rW1, const float* __restrict__ rb1,
                    const float* __restrict__ rW2, const float* __restrict__ rb2,
                    const float* __restrict__ rW3, const float* __restrict__ rb3,
                    float* __restrict__ out, int cur) {
    __shared__ float W1T[32 * 65];
    __shared__ float W2T[64 * 65];
    __shared__ float W3s[128], b1s[64], b2s[64];
    __shared__ float hb[8 * 32], y1b[8 * 64];
    int t = threadIdx.x;
    for (int idx = t; idx < 64 * 32; idx += 256) {
        int o = idx >> 5, d = idx & 31;
        W1T[d * 65 + o] = rW1[idx];
    }
    for (int idx = t; idx < 64 * 64; idx += 256) {
        int p = idx >> 6, o = idx & 63;
        W2T[o * 65 + p] = rW2[idx];
    }
    if (t < 128) W3s[t] = rW3[t];
    if (t < 64) { b1s[t] = rb1[t]; b2s[t] = rb2[t]; }

    int w = t >> 5, l = t & 31;
    int n = blockIdx.x * 8 + w;
    hb[w * 32 + l] = g_h[cur][n * 32 + l];
    __syncthreads();

#pragma unroll
    for (int oo = 0; oo < 2; oo++) {
        int o = l + oo * 32;
        float acc = b1s[o];
#pragma unroll 8
        for (int d = 0; d < 32; d++) acc = fmaf(W1T[d * 65 + o], hb[w * 32 + d], acc);
        y1b[w * 64 + o] = fmaxf(acc, 0.f);
    }
    __syncwarp();

    float o0 = 0.f, o1 = 0.f;
#pragma unroll
    for (int pp = 0; pp < 2; pp++) {
        int p = l + pp * 32;
        float acc = b2s[p];
#pragma unroll 8
        for (int o = 0; o < 64; o++) acc = fmaf(W2T[o * 65 + p], y1b[w * 64 + o], acc);
        acc = fmaxf(acc, 0.f);
        o0 = fmaf(W3s[p],      acc, o0);
        o1 = fmaf(W3s[64 + p], acc, o1);
    }
#pragma unroll
    for (int s = 16; s > 0; s >>= 1) {
        o0 += __shfl_xor_sync(0xffffffffu, o0, s);
        o1 += __shfl_xor_sync(0xffffffffu, o1, s);
    }
    if (l == 0) {
        o0 = fmaxf(o0 + rb3[0], 0.f);
        o1 = fmaxf(o1 + rb3[1], 0.f);
        out[n * 2 + 0] = 1.f / (1.f + expf(-o0));
        out[n * 2 + 1] = 1.f / (1.f + expf(-o1));
    }
}

extern "C" void kernel_launch(void* const* d_in, const int* in_sizes, int n_in,
                              void* d_out, int out_size) {
    const float* J   = (const float*)d_in[0];
    const float* b   = (const float*)d_in[1];
    const float* W1  = (const float*)d_in[2];   // mp_W1 (64 x 67)
    const float* b1  = (const float*)d_in[3];
    const float* W2  = (const float*)d_in[4];   // mp_W2 (64 x 64)
    const float* b2  = (const float*)d_in[5];
    const float* W3  = (const float*)d_in[6];   // mp_W3 (32 x 64)
    const float* b3  = (const float*)d_in[7];
    const float* Wih = (const float*)d_in[8];   // (96 x 64)
    const float* Whh = (const float*)d_in[9];   // (96 x 32)
    const float* bih = (const float*)d_in[10];
    const float* bhh = (const float*)d_in[11];
    const float* rW1 = (const float*)d_in[12];  // (64 x 32)
    const float* rb1 = (const float*)d_in[13];
    const float* rW2 = (const float*)d_in[14];  // (64 x 64)
    const float* rb2 = (const float*)d_in[15];
    const float* rW3 = (const float*)d_in[16];  // (2 x 64)
    const float* rb3 = (const float*)d_in[17];
    float* out = (float*)d_out;

    // >48KB dynamic smem opt-in (function attributes; idempotent, capture-safe)
    cudaFuncSetAttribute(edge_kernel,
                         cudaFuncAttributeMaxDynamicSharedMemorySize, SM_BYTES);
    cudaFuncSetAttribute(gru_node_kernel,
                         cudaFuncAttributeMaxDynamicSharedMemorySize, GN_BYTES);

    step0_kernel<<<128, 256>>>(b, W1, b1, W2, W3);
    int cur = 0;
    for (int s = 0; s < 5; s++) {
        dim3 grid(NN / TJ, NN / (2 * TI));   // (64, 16), 2 i-tiles per CTA
        edge_kernel<<<grid, 512, SM_BYTES>>>(J, b2, b3);
        gru_node_kernel<<<64, 256, GN_BYTES>>>(Wih, Whh, bih, bhh, b, W1, b1, cur);
        cur ^= 1;
    }
    readout_kernel<<<64, 256>>>(rW1, rb1, rW2, rb2, rW3, rb3, out, cur);
}

// round 12
// speedup vs baseline: 1.1534x; 1.1534x over previous
#include <cuda_runtime.h>
#include <math.h>

#define NN 512
#define D 32
#define TI 16
#define TJ 8
#define TE 128

typedef unsigned long long u64;

// packed f32x2 helpers (sm_103a; PTX ISA f32x2 ops)
#define FMA2ACC(acc, a, b) \
    asm("fma.rn.f32x2 %0, %1, %2, %0;" : "+l"(acc) : "l"(a), "l"(b))
#define PACK2(d, lo, hi) \
    asm("mov.b64 %0, {%1, %2};" : "=l"(d) : "f"(lo), "f"(hi))
#define UNPACK2(lo, hi, s) \
    asm("mov.b64 {%0, %1}, %2;" : "=f"(lo), "=f"(hi) : "l"(s))

// scratch (no allocation allowed)
__device__ float g_h[2][NN * D];
__device__ float g_Ai[NN * 64];
__device__ float g_Bj[NN * 64];
__device__ float g_ms[NN * D];
// pre-paired edge-MLP weights (built once per graph replay in step0)
__device__ u64 g_W2p[64 * 34];   // [o][k2]: (W2[o][2k2], W2[o][2k2+1]); stride 34 (272B = 16 mod 128)
__device__ u64 g_W3d[64 * 32];   // [k][c]:  (W3[c][k], W3[c][k]) duplicated
__device__ float g_wj[64];       // W1[:,64] gathered

// ---- Step-0: closed-form pre-factor (h0 = 0) + one-time weight pre-pairing -
__global__ void step0_kernel(const float* __restrict__ b,
                             const float* __restrict__ W1,
                             const float* __restrict__ b1,
                             const float* __restrict__ W2,
                             const float* __restrict__ W3) {
    int idx = blockIdx.x * 256 + threadIdx.x;   // 0 .. 32767
    int n = idx >> 6, k = idx & 63;
    float bn = b[n];
    g_Ai[n * 64 + k] = bn * W1[k * 67 + 65];
    g_Bj[n * 64 + k] = bn * W1[k * 67 + 66] + b1[k];
    if (idx < NN * 32) { g_ms[idx] = 0.f; g_h[0][idx] = 0.f; }
    if (idx < 64 * 32) {                       // W2 pair-pack: [o][k2]
        int o = idx >> 5, k2 = idx & 31;
        u64 v;
        PACK2(v, W2[o * 64 + 2 * k2], W2[o * 64 + 2 * k2 + 1]);
        g_W2p[o * 34 + k2] = v;
    }
    if (idx < 64 * 32) {                       // W3 dup-pack: [k][c]
        int kk = idx >> 5, c = idx & 31;
        float wv = W3[c * 64 + kk];
        u64 v;
        PACK2(v, wv, wv);
        g_W3d[kk * 32 + c] = v;
    }
    if (idx < 64) g_wj[idx] = W1[idx * 67 + 64];
}

// ---- Edge MLP as staged smem GEMM, 512 threads/CTA ------------------------
// Tile = 16 i x 8 j = 128 edges; 2 i-tiles per CTA, Ai/J register-prefetched.
// Phase A: m1 to smem. Phase B: m2 = relu(m1@W2^T+b2), 4e x 4o register tiles
// with PRE-PAIRED weights (no in-loop packing). Phase C: msg = relu(m2@W3^T+b3)
// with dup-packed W3; 16 warps x 2c; warp-local i-reduction; atomics to g_ms.
#define SM_M1   0        // [128][64] floats
#define SM_M2T  8192     // [64][132] floats
#define SM_W2P  16640    // 2176 u64 = 4352 floats  (byte off 66560, 16B-aligned)
#define SM_W3D  20992    // 2048 u64 = 4096 floats  (byte off 83968, 16B-aligned)
#define SM_AIS  25088    // [16][64]
#define SM_BJS  26112    // [8][64]
#define SM_JS   26624    // [128]
#define SM_WJS  26752    // [64]
#define SM_B2S  26816    // [64]
#define SM_B3S  26880    // [32]
#define SM_FLOATS 26912
#define SM_BYTES (SM_FLOATS * 4)

__global__ __launch_bounds__(512, 1)
void edge_kernel(const float* __restrict__ J,
                 const float* __restrict__ b2, const float* __restrict__ b3) {
    extern __shared__ float sm[];
    u64* smW2p = (u64*)&sm[SM_W2P];
    u64* smW3d = (u64*)&sm[SM_W3D];
    int t = threadIdx.x;
    int j0 = blockIdx.x * TJ;

    // --- prefetch tile 0's Ai (2 floats/thread) + J (1 float, t<128) -------
    int i0_0 = blockIdx.y * (2 * TI);
    float pfA0 = g_Ai[i0_0 * 64 + t];
    float pfA1 = g_Ai[i0_0 * 64 + 512 + t];
    float pfJ = 0.f;
    if (t < TE) pfJ = J[(i0_0 + (t >> 3)) * NN + j0 + (t & 7)];

    // weights pre-paired in global: linear copy, coalesced + conflict-free
    for (int idx = t; idx < 64 * 34; idx += 512) smW2p[idx] = g_W2p[idx];
    for (int idx = t; idx < 64 * 32; idx += 512) smW3d[idx] = g_W3d[idx];
    if (t < 64) { sm[SM_WJS + t] = g_wj[t]; sm[SM_B2S + t] = b2[t]; }
    if (t < 32) sm[SM_B3S + t] = b3[t];
    for (int idx = t; idx < TJ * 64; idx += 512)
        sm[SM_BJS + idx] = g_Bj[j0 * 64 + idx];

    for (int ii = 0; ii < 2; ii++) {
        __syncthreads();   // orders fills; protects AIS/JS/M1/M2T across iters
        sm[SM_AIS + t]       = pfA0;
        sm[SM_AIS + 512 + t] = pfA1;
        if (t < TE) sm[SM_JS + t] = pfJ;
        if (ii == 0) {
            int i0n = i0_0 + TI;
            pfA0 = g_Ai[i0n * 64 + t];
            pfA1 = g_Ai[i0n * 64 + 512 + t];
            if (t < TE) pfJ = J[(i0n + (t >> 3)) * NN + j0 + (t & 7)];
        }
        __syncthreads();

        // Phase A: m1[e][k] = relu(Ai + Bj + J*wJ);  e = i*8 + j
        for (int idx = t; idx < TE * 64; idx += 512) {
            int e = idx >> 6, k = idx & 63;
            float v = sm[SM_AIS + (e >> 3) * 64 + k] + sm[SM_BJS + (e & 7) * 64 + k]
                    + sm[SM_JS + e] * sm[SM_WJS + k];
            sm[SM_M1 + idx] = fmaxf(v, 0.f);
        }
        __syncthreads();

        // Phase B: m2t[o][e] = relu(m1 @ W2^T + b2); 4e x 4o per thread
        // o = og + 16*oo (strided map -> conflict-free 272B-row weight loads)
        {
            int og = t & 15, eg = t >> 4;      // og 0..15, eg 0..31
            u64 acc[4][4];
#pragma unroll
            for (int ee = 0; ee < 4; ee++)
#pragma unroll
                for (int oo = 0; oo < 4; oo++) acc[ee][oo] = 0ull;

#pragma unroll 4
            for (int kq = 0; kq < 16; kq++) {
                int k0 = kq * 4;
                int k2 = kq * 2;
                ulonglong2 m1v[4];
#pragma unroll
                for (int ee = 0; ee < 4; ee++)
                    m1v[ee] = *(const ulonglong2*)&sm[SM_M1 + (eg * 4 + ee) * 64 + k0];
                ulonglong2 wv[4];
#pragma unroll
                for (int oo = 0; oo < 4; oo++)
                    wv[oo] = *(const ulonglong2*)&smW2p[(og + 16 * oo) * 34 + k2];
#pragma unroll
                for (int ee = 0; ee < 4; ee++) {
#pragma unroll
                    for (int oo = 0; oo < 4; oo++) {
                        FMA2ACC(acc[ee][oo], wv[oo].x, m1v[ee].x);
                        FMA2ACC(acc[ee][oo], wv[oo].y, m1v[ee].y);
                    }
                }
            }
            // float4 store per o: e-values eg*4..eg*4+3 contiguous in M2T rows
#pragma unroll
            for (int oo = 0; oo < 4; oo++) {
                int o = og + 16 * oo;
                float bb = sm[SM_B2S + o];
                float4 f;
                float lo, hi;
                UNPACK2(lo, hi, acc[0][oo]); f.x = fmaxf(lo + hi + bb, 0.f);
                UNPACK2(lo, hi, acc[1][oo]); f.y = fmaxf(lo + hi + bb, 0.f);
                UNPACK2(lo, hi, acc[2][oo]); f.z = fmaxf(lo + hi + bb, 0.f);
                UNPACK2(lo, hi, acc[3][oo]); f.w = fmaxf(lo + hi + bb, 0.f);
                *(float4*)&sm[SM_M2T + o * 132 + eg * 4] = f;
            }
        }
        __syncthreads();

        // Phase C: msg = relu(m2 @ W3^T + b3); 16 warps x 2c; reduce over i
        {
            int w = t >> 5, l = t & 31;   // warp w -> c = 2w,2w+1; lane l -> e = 4l..4l+3
            u64 accp[2][2];
            accp[0][0] = accp[0][1] = accp[1][0] = accp[1][1] = 0ull;

#pragma unroll 4
            for (int k = 0; k < 64; k++) {
                ulonglong2 m2v = *(const ulonglong2*)&sm[SM_M2T + k * 132 + l * 4];
                ulonglong2 w3v = *(const ulonglong2*)&smW3d[k * 32 + w * 2];  // dup pairs, broadcast
                FMA2ACC(accp[0][0], w3v.x, m2v.x); FMA2ACC(accp[0][1], w3v.x, m2v.y);
                FMA2ACC(accp[1][0], w3v.y, m2v.x); FMA2ACC(accp[1][1], w3v.y, m2v.y);
            }
            float v[2][4];
#pragma unroll
            for (int cc = 0; cc < 2; cc++) {
                float bb = sm[SM_B3S + w * 2 + cc];
                float lo, hi;
                UNPACK2(lo, hi, accp[cc][0]);
                v[cc][0] = fmaxf(lo + bb, 0.f); v[cc][1] = fmaxf(hi + bb, 0.f);
                UNPACK2(lo, hi, accp[cc][1]);
                v[cc][2] = fmaxf(lo + bb, 0.f); v[cc][3] = fmaxf(hi + bb, 0.f);
            }
            // lane l: i = l>>1 (bits 1..4), j = 4*(l&1)+q. Reduce over i.
#pragma unroll
            for (int cc = 0; cc < 2; cc++)
#pragma unroll
                for (int q = 0; q < 4; q++) {
                    float x = v[cc][q];
                    x += __shfl_xor_sync(0xffffffffu, x, 2);
                    x += __shfl_xor_sync(0xffffffffu, x, 4);
                    x += __shfl_xor_sync(0xffffffffu, x, 8);
                    x += __shfl_xor_sync(0xffffffffu, x, 16);
                    v[cc][q] = x;
                }
            if (l < 2) {
#pragma unroll
                for (int cc = 0; cc < 2; cc++)
#pragma unroll
                    for (int q = 0; q < 4; q++)
                        atomicAdd(&g_ms[(j0 + l * 4 + q) * 32 + w * 2 + cc], v[cc][q]);
            }
        }
    }
}

// ---- Fused GRU + next-step pre-factor: WARP-PER-NODE, 64 CTAs -------------
#define GN_WIHT 0                    // [64][97]  Wih^T
#define GN_WHHT 6208                 // [32][97]  Whh^T
#define GN_W1T  9312                 // [64][65]  W1^T (cols 0..63)
#define GN_B1   13472
#define GN_WBI  13536
#define GN_WBJ  13600
#define GN_BIH  13664
#define GN_BHH  13760
#define GN_HB   13856                // 8*32
#define GN_MSB  14112                // 8*32
#define GN_HNB  14368                // 8*32
#define GN_FLOATS 14624
#define GN_BYTES (GN_FLOATS * 4)

__global__ __launch_bounds__(256, 1)
void gru_node_kernel(const float* __restrict__ Wih, const float* __restrict__ Whh,
                     const float* __restrict__ bih, const float* __restrict__ bhh,
                     const float* __restrict__ b,   const float* __restrict__ W1,
                     const float* __restrict__ b1,  int cur) {
    extern __shared__ float sm[];
    int t = threadIdx.x;
    for (int idx = t; idx < 96 * 64; idx += 256) {
        int q = idx >> 6, d = idx & 63;
        sm[GN_WIHT + d * 97 + q] = Wih[idx];
    }
    for (int idx = t; idx < 96 * 32; idx += 256) {
        int q = idx >> 5, d = idx & 31;
        sm[GN_WHHT + d * 97 + q] = Whh[idx];
    }
    for (int idx = t; idx < 64 * 64; idx += 256) {
        int k = idx >> 6, d = idx & 63;
        sm[GN_W1T + d * 65 + k] = W1[k * 67 + d];
    }
    if (t < 64) {
        sm[GN_B1 + t]  = b1[t];
        sm[GN_WBI + t] = W1[t * 67 + 65];
        sm[GN_WBJ + t] = W1[t * 67 + 66];
    }
    if (t < 96) { sm[GN_BIH + t] = bih[t]; sm[GN_BHH + t] = bhh[t]; }

    int w = t >> 5, l = t & 31;
    int n = blockIdx.x * 8 + w;
    int nxt = cur ^ 1;
    float hl  = g_h[cur][n * 32 + l];
    float msl = g_ms[n * 32 + l];
    sm[GN_HB  + w * 32 + l] = hl;
    sm[GN_MSB + w * 32 + l] = msl;
    __syncthreads();

    float gir = sm[GN_BIH + l], giz = sm[GN_BIH + 32 + l], gin = sm[GN_BIH + 64 + l];
    float ghr = sm[GN_BHH + l], ghz = sm[GN_BHH + 32 + l], ghn = sm[GN_BHH + 64 + l];
    const float* hb = &sm[GN_HB  + w * 32];
    const float* mb = &sm[GN_MSB + w * 32];
#pragma unroll 8
    for (int d = 0; d < 32; d++) {
        float hd = hb[d], md = mb[d];
        const float* c1 = &sm[GN_WIHT + d * 97];
        const float* c2 = &sm[GN_WIHT + (32 + d) * 97];
        gir = fmaf(c1[l],      hd, gir); gir = fmaf(c2[l],      md, gir);
        giz = fmaf(c1[32 + l], hd, giz); giz = fmaf(c2[32 + l], md, giz);
        gin = fmaf(c1[64 + l], hd, gin); gin = fmaf(c2[64 + l], md, gin);
        const float* c3 = &sm[GN_WHHT + d * 97];
        ghr = fmaf(c3[l],      hd, ghr);
        ghz = fmaf(c3[32 + l], hd, ghz);
        ghn = fmaf(c3[64 + l], hd, ghn);
    }
    float r  = 1.f / (1.f + expf(-(gir + ghr)));
    float z  = 1.f / (1.f + expf(-(giz + ghz)));
    float ng = tanhf(gin + r * ghn);
    float hn = (1.f - z) * ng + z * hl;
    g_h[nxt][n * 32 + l] = hn;
    sm[GN_HNB + w * 32 + l] = hn;
    g_ms[n * 32 + l] = 0.f;
    __syncwarp();

    float bn = b[n];
    const float* hnb = &sm[GN_HNB + w * 32];
#pragma unroll
    for (int kk = 0; kk < 2; kk++) {
        int k = l + kk * 32;
        float a = bn * sm[GN_WBI + k];
        float c = bn * sm[GN_WBJ + k] + sm[GN_B1 + k];
#pragma unroll 8
        for (int d = 0; d < 32; d++) {
            float hd = hnb[d];
            a = fmaf(sm[GN_W1T + d * 65 + k],        hd, a);
            c = fmaf(sm[GN_W1T + (32 + d) * 65 + k], hd, c);
        }
        g_Ai[n * 64 + k] = a;
        g_Bj[n * 64 + k] = c;
    }
}

// ---- Readout MLP + sigmoid: WARP-PER-NODE, 64 CTAs ------------------------
__global__ __launch_bounds__(256)
void readout_kernel(const float* __restrict__ rW1, const float* __restrict__ rb1,
                    const float* __restrict__ rW2, const float* __restrict__ rb2,
                    const float* __restrict__ rW3, const float* __restrict__ rb3,
                    float* __restrict__ out, int cur) {
    __shared__ float W1T[32 * 65];
    __shared__ float W2T[64 * 65];
    __shared__ float W3s[128], b1s[64], b2s[64];
    __shared__ float hb[8 * 32], y1b[8 * 64];
    int t = threadIdx.x;
    for (int idx = t; idx < 64 * 32; idx += 256) {
        int o = idx >> 5, d = idx & 31;
        W1T[d * 65 + o] = rW1[idx];
    }
    for (int idx = t; idx < 64 * 64; idx += 256) {
        int p = idx >> 6, o = idx & 63;
        W2T[o * 65 + p] = rW2[idx];
    }
    if (t < 128) W3s[t] = rW3[t];
    if (t < 64) { b1s[t] = rb1[t]; b2s[t] = rb2[t]; }

    int w = t >> 5, l = t & 31;
    int n = blockIdx.x * 8 + w;
    hb[w * 32 + l] = g_h[cur][n * 32 + l];
    __syncthreads();

#pragma unroll
    for (int oo = 0; oo < 2; oo++) {
        int o = l + oo * 32;
        float acc = b1s[o];
#pragma unroll 8
        for (int d = 0; d < 32; d++) acc = fmaf(W1T[d * 65 + o], hb[w * 32 + d], acc);
        y1b[w * 64 + o] = fmaxf(acc, 0.f);
    }
    __syncwarp();

    float o0 = 0.f, o1 = 0.f;
#pragma unroll
    for (int pp = 0; pp < 2; pp++) {
        int p = l + pp * 32;
        float acc = b2s[p];
#pragma unroll 8
        for (int o = 0; o < 64; o++) acc = fmaf(W2T[o * 65 + p], y1b[w * 64 + o], acc);
        acc = fmaxf(acc, 0.f);
        o0 = fmaf(W3s[p],      acc, o0);
        o1 = fmaf(W3s[64 + p], acc, o1);
    }
#pragma unroll
    for (int s = 16; s > 0; s >>= 1) {
        o0 += __shfl_xor_sync(0xffffffffu, o0, s);
        o1 += __shfl_xor_sync(0xffffffffu, o1, s);
    }
    if (l == 0) {
        o0 = fmaxf(o0 + rb3[0], 0.f);
        o1 = fmaxf(o1 + rb3[1], 0.f);
        out[n * 2 + 0] = 1.f / (1.f + expf(-o0));
        out[n * 2 + 1] = 1.f / (1.f + expf(-o1));
    }
}

extern "C" void kernel_launch(void* const* d_in, const int* in_sizes, int n_in,
                              void* d_out, int out_size) {
    const float* J   = (const float*)d_in[0];
    const float* b   = (const float*)d_in[1];
    const float* W1  = (const float*)d_in[2];   // mp_W1 (64 x 67)
    const float* b1  = (const float*)d_in[3];
    const float* W2  = (const float*)d_in[4];   // mp_W2 (64 x 64)
    const float* b2  = (const float*)d_in[5];
    const float* W3  = (const float*)d_in[6];   // mp_W3 (32 x 64)
    const float* b3  = (const float*)d_in[7];
    const float* Wih = (const float*)d_in[8];   // (96 x 64)
    const float* Whh = (const float*)d_in[9];   // (96 x 32)
    const float* bih = (const float*)d_in[10];
    const float* bhh = (const float*)d_in[11];
    const float* rW1 = (const float*)d_in[12];  // (64 x 32)
    const float* rb1 = (const float*)d_in[13];
    const float* rW2 = (const float*)d_in[14];  // (64 x 64)
    const float* rb2 = (const float*)d_in[15];
    const float* rW3 = (const float*)d_in[16];  // (2 x 64)
    const float* rb3 = (const float*)d_in[17];
    float* out = (float*)d_out;

    // >48KB dynamic smem opt-in (function attributes; idempotent, capture-safe)
    cudaFuncSetAttribute(edge_kernel,
                         cudaFuncAttributeMaxDynamicSharedMemorySize, SM_BYTES);
    cudaFuncSetAttribute(gru_node_kernel,
                         cudaFuncAttributeMaxDynamicSharedMemorySize, GN_BYTES);

    step0_kernel<<<128, 256>>>(b, W1, b1, W2, W3);
    int cur = 0;
    for (int s = 0; s < 5; s++) {
        dim3 grid(NN / TJ, NN / (2 * TI));   // (64, 16), 2 i-tiles per CTA
        edge_kernel<<<grid, 512, SM_BYTES>>>(J, b2, b3);
        gru_node_kernel<<<64, 256, GN_BYTES>>>(Wih, Whh, bih, bhh, b, W1, b1, cur);
        cur ^= 1;
    }
    readout_kernel<<<64, 256>>>(rW1, rb1, rW2, rb2, rW3, rb3, out, cur);
}